// round 7
// baseline (speedup 1.0000x reference)
#include <cuda_runtime.h>
#include <cuda_fp16.h>
#include <math.h>
#include <stdint.h>

#define N_TOK 4096
#define DIMD  1024
#define HID   4096
#define OUTD  1024
#define NE    8
#define RMAX  (2*N_TOK)

// ---------------- scratch (static device globals) ----------------
__device__ __half g_xh[(size_t)N_TOK * DIMD];      //  8 MB x in fp16 (token order)
__device__ __half g_hh[(size_t)RMAX * HID];        // 64 MB GEMM1 out (fp16, expert-sorted)
__device__ __half g_w1h[(size_t)NE * DIMD * HID];  // 64 MB
__device__ __half g_w2h[(size_t)NE * HID * OUTD];  // 64 MB
__device__ int   g_perm[RMAX];
__device__ float g_wgt[RMAX];
__device__ int   g_sel[N_TOK * 2];
__device__ float g_w[N_TOK * 2];
__device__ int   g_cnt[NE];
__device__ int   g_off[NE];

// ---------------- helpers ----------------
__device__ __forceinline__ void cp16(void* dst, const void* src) {
    unsigned sd = (unsigned)__cvta_generic_to_shared(dst);
    asm volatile("cp.async.cg.shared.global [%0], [%1], 16;" :: "r"(sd), "l"(src));
}
__device__ __forceinline__ uint32_t smem_u32(const void* p) {
    uint32_t a;
    asm("{ .reg .u64 t; cvta.to.shared.u64 t, %1; cvt.u32.u64 %0, t; }" : "=r"(a) : "l"(p));
    return a;
}
__device__ __forceinline__ void ldm4(uint32_t r[4], uint32_t addr) {
    asm volatile("ldmatrix.sync.aligned.m8n8.x4.shared.b16 {%0,%1,%2,%3}, [%4];"
        : "=r"(r[0]), "=r"(r[1]), "=r"(r[2]), "=r"(r[3]) : "r"(addr));
}
__device__ __forceinline__ void ldm4t(uint32_t r[4], uint32_t addr) {
    asm volatile("ldmatrix.sync.aligned.m8n8.x4.trans.shared.b16 {%0,%1,%2,%3}, [%4];"
        : "=r"(r[0]), "=r"(r[1]), "=r"(r[2]), "=r"(r[3]) : "r"(addr));
}
__device__ __forceinline__ void mma16816(float c[4], const uint32_t a[4], const uint32_t* b) {
    asm volatile("mma.sync.aligned.m16n8k16.row.col.f32.f16.f16.f32 "
        "{%0,%1,%2,%3}, {%4,%5,%6,%7}, {%8,%9}, {%0,%1,%2,%3};"
        : "+f"(c[0]), "+f"(c[1]), "+f"(c[2]), "+f"(c[3])
        : "r"(a[0]), "r"(a[1]), "r"(a[2]), "r"(a[3]), "r"(b[0]), "r"(b[1]));
}

#define SW128(x) ((x) ^ (((x) >> 3) & 0x70))
#define STAGE   49152
#define SMEM_TOTAL (4 * STAGE)

// ---------------- zero output (graph-replayed; out is poisoned each run) ----------------
__global__ void zero_out_kernel(float4* __restrict__ out) {
    out[blockIdx.x * 256 + threadIdx.x] = make_float4(0.f, 0.f, 0.f, 0.f);
}

// ---------------- x -> fp16 (token order; independent of routing) ----------------
__global__ void convx_kernel(const float4* __restrict__ x) {
    int i = blockIdx.x * 256 + threadIdx.x;
    float4 v = x[i];
    __half2* dst = (__half2*)g_xh;
    dst[2*i]   = __floats2half2_rn(v.x, v.y);
    dst[2*i+1] = __floats2half2_rn(v.z, v.w);
}

// ---------------- gate: warp-per-token, shuffle reduce ----------------
__global__ void gate_kernel(const float* __restrict__ x, const float* __restrict__ Wg) {
    const int wid  = threadIdx.x >> 5, lane = threadIdx.x & 31;
    const int n    = blockIdx.x * 8 + wid;
    const float* xr = x + (size_t)n * DIMD;

    float acc[NE];
#pragma unroll
    for (int e = 0; e < NE; e++) acc[e] = 0.f;
#pragma unroll 4
    for (int i = 0; i < DIMD / 32; i++) {
        int d = lane + 32 * i;
        float xv = xr[d];
        const float4* wr = (const float4*)(Wg + (size_t)d * NE);
        float4 w0 = wr[0], w1 = wr[1];
        acc[0] += xv * w0.x; acc[1] += xv * w0.y; acc[2] += xv * w0.z; acc[3] += xv * w0.w;
        acc[4] += xv * w1.x; acc[5] += xv * w1.y; acc[6] += xv * w1.z; acc[7] += xv * w1.w;
    }
#pragma unroll
    for (int e = 0; e < NE; e++) {
#pragma unroll
        for (int s = 16; s > 0; s >>= 1)
            acc[e] += __shfl_xor_sync(0xFFFFFFFFu, acc[e], s);
    }
    if (lane == 0) {
        float v[NE];
#pragma unroll
        for (int e = 0; e < NE; e++) v[e] = fmaxf(acc[e], 0.f);
        int e0 = 0; float p0 = v[0];
        int e1 = -1; float p1 = -1.f;
#pragma unroll
        for (int e = 1; e < NE; e++) {
            if (v[e] > p0)      { p1 = p0; e1 = e0; p0 = v[e]; e0 = e; }
            else if (v[e] > p1) { p1 = v[e]; e1 = e; }
        }
        float w0 = 1.f / (1.f + expf(p1 - p0));
        g_sel[2*n] = e0; g_sel[2*n+1] = e1;
        g_w[2*n] = w0;   g_w[2*n+1] = 1.f - w0;
    }
}

// ---------------- plan: deterministic scan-based ranking ----------------
__global__ void plan_kernel() {
    __shared__ int cnt_s[NE][1024];
    __shared__ int off_s[NE], tot_s[NE];
    const int tid = threadIdx.x;
    const int wid = tid >> 5, lane = tid & 31;

    int sel8[8];
    int c[NE];
#pragma unroll
    for (int e = 0; e < NE; e++) c[e] = 0;
#pragma unroll
    for (int j = 0; j < 8; j++) {
        sel8[j] = g_sel[tid * 8 + j];
        c[sel8[j]]++;
    }
#pragma unroll
    for (int e = 0; e < NE; e++) cnt_s[e][tid] = c[e];
    __syncthreads();

    if (wid < NE) {
        int s = 0;
#pragma unroll
        for (int j = 0; j < 32; j++) s += cnt_s[wid][lane * 32 + j];
        int incl = s;
#pragma unroll
        for (int d = 1; d < 32; d <<= 1) {
            int v = __shfl_up_sync(0xFFFFFFFFu, incl, d);
            if (lane >= d) incl += v;
        }
        int run = incl - s;
        if (lane == 31) tot_s[wid] = incl;
#pragma unroll
        for (int j = 0; j < 32; j++) {
            int v = cnt_s[wid][lane * 32 + j];
            cnt_s[wid][lane * 32 + j] = run;
            run += v;
        }
    }
    __syncthreads();
    if (tid == 0) {
        int o = 0;
        for (int e = 0; e < NE; e++) {
            off_s[e] = o; g_off[e] = o; g_cnt[e] = tot_s[e]; o += tot_s[e];
        }
    }
    __syncthreads();

    int pref[NE];
#pragma unroll
    for (int e = 0; e < NE; e++) pref[e] = off_s[e] + cnt_s[e][tid];
#pragma unroll
    for (int j = 0; j < 8; j++) {
        int i = tid * 8 + j;
        int e = sel8[j];
        int r = pref[e]++;
        g_perm[r] = i >> 1;
        g_wgt[r]  = g_w[i];
    }
}

// weight convert fp32 -> fp16
template<bool FIRST>
__global__ void convert_kernel(const float4* __restrict__ src, int n4) {
    __half2* dst = (__half2*)(FIRST ? g_w1h : g_w2h);
    for (int i = blockIdx.x * blockDim.x + threadIdx.x; i < n4; i += gridDim.x * blockDim.x) {
        float4 v = src[i];
        dst[2*i]   = __floats2half2_rn(v.x, v.y);
        dst[2*i+1] = __floats2half2_rn(v.z, v.w);
    }
}

// ---------------- fp16 HMMA GEMM ----------------
// FIRST: A = g_xh via g_perm indirection, C = g_hh (fp16, expert-sorted)
// !FIRST: A = g_hh direct, epilogue scatters w*relu(.) into out via atomicAdd (RED)
template<int KD, int ND, bool FIRST>
__global__ __launch_bounds__(256, 1)
void gemm_hmma(const float* __restrict__ biasBase, float* __restrict__ out)
{
    extern __shared__ __align__(128) char smem[];
    const int e    = blockIdx.z;
    const int cnt  = g_cnt[e];
    const int row0 = blockIdx.x * 128;
    if (row0 >= cnt) return;
    const int base = g_off[e];
    const int col0 = blockIdx.y * 256;

    const __half* Asrc = FIRST ? g_xh : g_hh;
    const __half* B    = (FIRST ? g_w1h : g_w2h) + (size_t)e * KD * ND + col0;
    const float*  bias = biasBase + (size_t)e * ND + col0;

    const uint32_t sb  = smem_u32(smem);
    const int tid = threadIdx.x;
    const int wid = tid >> 5, lane = tid & 31;
    const int wm = wid >> 2, wn = wid & 3;
    const int lq = lane >> 2, lr = lane & 3;
    const int ls = lane & 7;

    int aoff[4];
#pragma unroll
    for (int i = 0; i < 4; i++) {
        int r  = (tid >> 3) + 32 * i;
        int gr = row0 + r;
        int cr = (gr < cnt) ? gr : 0;
        aoff[i] = (FIRST ? g_perm[base + cr] : (base + cr)) * KD;
    }
    const int aj = tid & 7;
    const int bc = tid & 31;
    const int bkl = tid >> 5;

    auto fill = [&](int kt) {
        char* st = smem + (size_t)(kt & 3) * STAGE;
#pragma unroll
        for (int i = 0; i < 4; i++) {
            int r = (tid >> 3) + 32 * i;
            cp16(st + SW128(r * 128 + aj * 16), Asrc + aoff[i] + kt * 64 + aj * 8);
        }
#pragma unroll
        for (int i = 0; i < 8; i++) {
            int k = bkl + 8 * i;
            cp16(st + 16384 + k * 512 + ((bc ^ bkl) << 4),
                 B + (size_t)(kt * 64 + k) * ND + bc * 8);
        }
        asm volatile("cp.async.commit_group;");
    };

    const int KT = KD / 64;
    fill(0); fill(1); fill(2);

    float acc[4][8][4];
#pragma unroll
    for (int f = 0; f < 4; f++)
#pragma unroll
        for (int g = 0; g < 8; g++)
#pragma unroll
            for (int q = 0; q < 4; q++) acc[f][g][q] = 0.f;

    const uint32_t aRowB = (uint32_t)(wm * 64 + ((lane >> 3) & 1) * 8 + ls) * 128;
    const uint32_t aCh   = (uint32_t)(lane >> 4);
    const uint32_t bRowB = (uint32_t)(((lane >> 3) & 1) * 8 + ls) * 512;
    const uint32_t bC0   = (uint32_t)(wn * 8 + (lane >> 4));

#pragma unroll 1
    for (int kt = 0; kt < KT; kt++) {
        const int rem = KT - 1 - kt;
        if (rem >= 2)      asm volatile("cp.async.wait_group 2;");
        else if (rem == 1) asm volatile("cp.async.wait_group 1;");
        else               asm volatile("cp.async.wait_group 0;");
        __syncthreads();
        if (kt + 3 < KT) fill(kt + 3);

        const uint32_t sA = sb + (uint32_t)(kt & 3) * STAGE;
        const uint32_t sB = sA + 16384;
#pragma unroll
        for (int ks = 0; ks < 4; ks++) {
            uint32_t a[4][4], b[4][4];
#pragma unroll
            for (int f = 0; f < 4; f++)
                ldm4(a[f], sA + aRowB + f * 2048 + (((2 * ks + aCh) ^ ls) << 4));
#pragma unroll
            for (int p = 0; p < 4; p++)
                ldm4t(b[p], sB + ks * 8192 + bRowB + (((bC0 + 2 * p) ^ ls) << 4));
#pragma unroll
            for (int f = 0; f < 4; f++)
#pragma unroll
                for (int g = 0; g < 8; g++)
                    mma16816(acc[f][g], a[f], &b[g >> 1][(g & 1) * 2]);
        }
    }

    // ---- epilogue ----
#pragma unroll
    for (int f = 0; f < 4; f++) {
        const int r0 = row0 + wm * 64 + f * 16 + lq;
        const int r1 = r0 + 8;
        int   n0 = 0, n1 = 0;
        float wv0 = 0.f, wv1 = 0.f;
        if (!FIRST) {
            if (r0 < cnt) { n0 = g_perm[base + r0]; wv0 = g_wgt[base + r0]; }
            if (r1 < cnt) { n1 = g_perm[base + r1]; wv1 = g_wgt[base + r1]; }
        }
#pragma unroll
        for (int g = 0; g < 8; g++) {
            const int col = wn * 64 + g * 8 + 2 * lr;
            float2 bb = *(const float2*)(bias + col);
            float v00 = fmaxf(acc[f][g][0] + bb.x, 0.f);
            float v01 = fmaxf(acc[f][g][1] + bb.y, 0.f);
            float v10 = fmaxf(acc[f][g][2] + bb.x, 0.f);
            float v11 = fmaxf(acc[f][g][3] + bb.y, 0.f);
            if (FIRST) {
                if (r0 < cnt)
                    *(__half2*)(g_hh + (size_t)(base + r0) * ND + col0 + col) = __floats2half2_rn(v00, v01);
                if (r1 < cnt)
                    *(__half2*)(g_hh + (size_t)(base + r1) * ND + col0 + col) = __floats2half2_rn(v10, v11);
            } else {
                if (r0 < cnt) {
                    float* p = out + (size_t)n0 * ND + col0 + col;
                    atomicAdd(p,     wv0 * v00);
                    atomicAdd(p + 1, wv0 * v01);
                }
                if (r1 < cnt) {
                    float* p = out + (size_t)n1 * ND + col0 + col;
                    atomicAdd(p,     wv1 * v10);
                    atomicAdd(p + 1, wv1 * v11);
                }
            }
        }
    }
}

// ---------------- launch ----------------
extern "C" void kernel_launch(void* const* d_in, const int* in_sizes, int n_in,
                              void* d_out, int out_size) {
    const float* x  = (const float*)d_in[0];
    const float* Wg = (const float*)d_in[1];
    const float* W1 = (const float*)d_in[2];
    const float* b1 = (const float*)d_in[3];
    const float* W2 = (const float*)d_in[4];
    const float* b2 = (const float*)d_in[5];
    float* out = (float*)d_out;

    static cudaStream_t s1 = nullptr;
    static cudaEvent_t evFork = nullptr, evC1 = nullptr, evC2 = nullptr;
    static bool inited = false;
    if (!inited) {
        cudaStreamCreateWithFlags(&s1, cudaStreamNonBlocking);
        cudaEventCreateWithFlags(&evFork, cudaEventDisableTiming);
        cudaEventCreateWithFlags(&evC1,  cudaEventDisableTiming);
        cudaEventCreateWithFlags(&evC2,  cudaEventDisableTiming);
        cudaFuncSetAttribute(gemm_hmma<DIMD, HID, true>,
                             cudaFuncAttributeMaxDynamicSharedMemorySize, SMEM_TOTAL);
        cudaFuncSetAttribute(gemm_hmma<HID, OUTD, false>,
                             cudaFuncAttributeMaxDynamicSharedMemorySize, SMEM_TOTAL);
        inited = true;
    }

    // fork: weight converts on side stream
    cudaEventRecord(evFork, 0);
    cudaStreamWaitEvent(s1, evFork, 0);
    convert_kernel<true ><<<4096, 256, 0, s1>>>((const float4*)W1, NE * DIMD * HID / 4);
    cudaEventRecord(evC1, s1);
    convert_kernel<false><<<4096, 256, 0, s1>>>((const float4*)W2, NE * HID * OUTD / 4);
    cudaEventRecord(evC2, s1);

    // main: zero out, x->fp16, routing
    zero_out_kernel<<<N_TOK * OUTD / 1024, 256>>>((float4*)out);
    convx_kernel<<<N_TOK * DIMD / 1024, 256>>>((const float4*)x);
    gate_kernel<<<N_TOK / 8, 256>>>(x, Wg);
    plan_kernel<<<1, 1024>>>();

    // GEMM1 (A via perm indirection)
    cudaStreamWaitEvent(0, evC1, 0);
    {
        dim3 grid(RMAX / 128, HID / 256, NE);
        gemm_hmma<DIMD, HID, true><<<grid, 256, SMEM_TOTAL>>>(b1, nullptr);
    }
    // GEMM2 (fused weighted scatter into out)
    cudaStreamWaitEvent(0, evC2, 0);
    {
        dim3 grid(RMAX / 128, OUTD / 256, NE);
        gemm_hmma<HID, OUTD, false><<<grid, 256, SMEM_TOTAL>>>(b2, out);
    }
}

// round 8
// speedup vs baseline: 1.0279x; 1.0279x over previous
#include <cuda_runtime.h>
#include <cuda_fp16.h>
#include <math.h>
#include <stdint.h>

#define N_TOK 4096
#define DIMD  1024
#define HID   4096
#define OUTD  1024
#define NE    8
#define RMAX  (2*N_TOK)

// ---------------- scratch (static device globals) ----------------
__device__ __half g_xh[(size_t)N_TOK * DIMD];      //  8 MB x in fp16 (token order)
__device__ __half g_hh[(size_t)RMAX * HID];        // 64 MB GEMM1 out (fp16, expert-sorted)
__device__ float  g_ybuf[(size_t)RMAX * OUTD];     // 32 MB GEMM2 out
__device__ __half g_w1h[(size_t)NE * DIMD * HID];  // 64 MB
__device__ __half g_w2h[(size_t)NE * HID * OUTD];  // 64 MB
__device__ int   g_perm[RMAX];
__device__ float g_wgt[RMAX];
__device__ int   g_rowpos[N_TOK * 2];
__device__ int   g_sel[N_TOK * 2];
__device__ float g_w[N_TOK * 2];
__device__ int   g_cnt[NE];
__device__ int   g_off[NE];

// ---------------- helpers ----------------
__device__ __forceinline__ void cp16(void* dst, const void* src) {
    unsigned sd = (unsigned)__cvta_generic_to_shared(dst);
    asm volatile("cp.async.cg.shared.global [%0], [%1], 16;" :: "r"(sd), "l"(src));
}
__device__ __forceinline__ uint32_t smem_u32(const void* p) {
    uint32_t a;
    asm("{ .reg .u64 t; cvta.to.shared.u64 t, %1; cvt.u32.u64 %0, t; }" : "=r"(a) : "l"(p));
    return a;
}
__device__ __forceinline__ void ldm4(uint32_t r[4], uint32_t addr) {
    asm volatile("ldmatrix.sync.aligned.m8n8.x4.shared.b16 {%0,%1,%2,%3}, [%4];"
        : "=r"(r[0]), "=r"(r[1]), "=r"(r[2]), "=r"(r[3]) : "r"(addr));
}
__device__ __forceinline__ void ldm4t(uint32_t r[4], uint32_t addr) {
    asm volatile("ldmatrix.sync.aligned.m8n8.x4.trans.shared.b16 {%0,%1,%2,%3}, [%4];"
        : "=r"(r[0]), "=r"(r[1]), "=r"(r[2]), "=r"(r[3]) : "r"(addr));
}
__device__ __forceinline__ void mma16816(float c[4], const uint32_t a[4], const uint32_t* b) {
    asm volatile("mma.sync.aligned.m16n8k16.row.col.f32.f16.f16.f32 "
        "{%0,%1,%2,%3}, {%4,%5,%6,%7}, {%8,%9}, {%0,%1,%2,%3};"
        : "+f"(c[0]), "+f"(c[1]), "+f"(c[2]), "+f"(c[3])
        : "r"(a[0]), "r"(a[1]), "r"(a[2]), "r"(a[3]), "r"(b[0]), "r"(b[1]));
}

#define SW128(x) ((x) ^ (((x) >> 3) & 0x70))
#define STAGE   49152
#define SMEM_TOTAL (4 * STAGE)

// ---------------- fused gate + x->fp16: warp per token ----------------
__global__ void gate_kernel(const float* __restrict__ x, const float* __restrict__ Wg) {
    const int wid  = threadIdx.x >> 5, lane = threadIdx.x & 31;
    const int n    = blockIdx.x * 8 + wid;
    const float* xr = x + (size_t)n * DIMD;
    __half2* xhr = (__half2*)(g_xh + (size_t)n * DIMD);

    float acc[NE];
#pragma unroll
    for (int e = 0; e < NE; e++) acc[e] = 0.f;
#pragma unroll 4
    for (int i = 0; i < DIMD / 64; i++) {
        int d = 64 * i + 2 * lane;
        float2 xv = *(const float2*)(xr + d);
        xhr[d >> 1] = __floats2half2_rn(xv.x, xv.y);
        const float4* wr0 = (const float4*)(Wg + (size_t)d * NE);
        const float4* wr1 = (const float4*)(Wg + (size_t)(d + 1) * NE);
        float4 a0 = wr0[0], a1 = wr0[1], b0 = wr1[0], b1 = wr1[1];
        acc[0] += xv.x * a0.x + xv.y * b0.x;
        acc[1] += xv.x * a0.y + xv.y * b0.y;
        acc[2] += xv.x * a0.z + xv.y * b0.z;
        acc[3] += xv.x * a0.w + xv.y * b0.w;
        acc[4] += xv.x * a1.x + xv.y * b1.x;
        acc[5] += xv.x * a1.y + xv.y * b1.y;
        acc[6] += xv.x * a1.z + xv.y * b1.z;
        acc[7] += xv.x * a1.w + xv.y * b1.w;
    }
#pragma unroll
    for (int e = 0; e < NE; e++) {
#pragma unroll
        for (int s = 16; s > 0; s >>= 1)
            acc[e] += __shfl_xor_sync(0xFFFFFFFFu, acc[e], s);
    }
    if (lane == 0) {
        float v[NE];
#pragma unroll
        for (int e = 0; e < NE; e++) v[e] = fmaxf(acc[e], 0.f);
        int e0 = 0; float p0 = v[0];
        int e1 = -1; float p1 = -1.f;
#pragma unroll
        for (int e = 1; e < NE; e++) {
            if (v[e] > p0)      { p1 = p0; e1 = e0; p0 = v[e]; e0 = e; }
            else if (v[e] > p1) { p1 = v[e]; e1 = e; }
        }
        float w0 = 1.f / (1.f + expf(p1 - p0));
        g_sel[2*n] = e0; g_sel[2*n+1] = e1;
        g_w[2*n] = w0;   g_w[2*n+1] = 1.f - w0;
    }
}

// ---------------- plan: deterministic scan-based ranking ----------------
__global__ void plan_kernel() {
    __shared__ int cnt_s[NE][1024];
    __shared__ int off_s[NE], tot_s[NE];
    const int tid = threadIdx.x;
    const int wid = tid >> 5, lane = tid & 31;

    int sel8[8];
    int c[NE];
#pragma unroll
    for (int e = 0; e < NE; e++) c[e] = 0;
#pragma unroll
    for (int j = 0; j < 8; j++) {
        sel8[j] = g_sel[tid * 8 + j];
        c[sel8[j]]++;
    }
#pragma unroll
    for (int e = 0; e < NE; e++) cnt_s[e][tid] = c[e];
    __syncthreads();

    if (wid < NE) {
        int s = 0;
#pragma unroll
        for (int j = 0; j < 32; j++) s += cnt_s[wid][lane * 32 + j];
        int incl = s;
#pragma unroll
        for (int d = 1; d < 32; d <<= 1) {
            int v = __shfl_up_sync(0xFFFFFFFFu, incl, d);
            if (lane >= d) incl += v;
        }
        int run = incl - s;
        if (lane == 31) tot_s[wid] = incl;
#pragma unroll
        for (int j = 0; j < 32; j++) {
            int v = cnt_s[wid][lane * 32 + j];
            cnt_s[wid][lane * 32 + j] = run;
            run += v;
        }
    }
    __syncthreads();
    if (tid == 0) {
        int o = 0;
        for (int e = 0; e < NE; e++) {
            off_s[e] = o; g_off[e] = o; g_cnt[e] = tot_s[e]; o += tot_s[e];
        }
    }
    __syncthreads();

    int pref[NE];
#pragma unroll
    for (int e = 0; e < NE; e++) pref[e] = off_s[e] + cnt_s[e][tid];
#pragma unroll
    for (int j = 0; j < 8; j++) {
        int i = tid * 8 + j;
        int e = sel8[j];
        int r = pref[e]++;
        g_perm[r]   = i >> 1;
        g_wgt[r]    = g_w[i];
        g_rowpos[i] = r;
    }
}

// weight convert fp32 -> fp16
template<bool FIRST>
__global__ void convert_kernel(const float4* __restrict__ src, int n4) {
    __half2* dst = (__half2*)(FIRST ? g_w1h : g_w2h);
    for (int i = blockIdx.x * blockDim.x + threadIdx.x; i < n4; i += gridDim.x * blockDim.x) {
        float4 v = src[i];
        dst[2*i]   = __floats2half2_rn(v.x, v.y);
        dst[2*i+1] = __floats2half2_rn(v.z, v.w);
    }
}

// ---------------- fp16 HMMA GEMM ----------------
// FIRST: A = g_xh via g_perm indirection, C = g_hh (fp16, expert-sorted)
// !FIRST: A = g_hh direct, C = g_ybuf (fp32, expert-sorted)
template<int KD, int ND, bool FIRST>
__global__ __launch_bounds__(256, 1)
void gemm_hmma(const float* __restrict__ biasBase)
{
    extern __shared__ __align__(128) char smem[];
    const int e    = blockIdx.z;
    const int cnt  = g_cnt[e];
    const int row0 = blockIdx.x * 128;
    if (row0 >= cnt) return;
    const int base = g_off[e];
    const int col0 = blockIdx.y * 256;

    const __half* Asrc = FIRST ? g_xh : g_hh;
    const __half* B    = (FIRST ? g_w1h : g_w2h) + (size_t)e * KD * ND + col0;
    const float*  bias = biasBase + (size_t)e * ND + col0;

    const uint32_t sb  = smem_u32(smem);
    const int tid = threadIdx.x;
    const int wid = tid >> 5, lane = tid & 31;
    const int wm = wid >> 2, wn = wid & 3;
    const int lq = lane >> 2, lr = lane & 3;
    const int ls = lane & 7;

    int aoff[4];
#pragma unroll
    for (int i = 0; i < 4; i++) {
        int r  = (tid >> 3) + 32 * i;
        int gr = row0 + r;
        int cr = (gr < cnt) ? gr : 0;
        aoff[i] = (FIRST ? g_perm[base + cr] : (base + cr)) * KD;
    }
    const int aj = tid & 7;
    const int bc = tid & 31;
    const int bkl = tid >> 5;

    auto fill = [&](int kt) {
        char* st = smem + (size_t)(kt & 3) * STAGE;
#pragma unroll
        for (int i = 0; i < 4; i++) {
            int r = (tid >> 3) + 32 * i;
            cp16(st + SW128(r * 128 + aj * 16), Asrc + aoff[i] + kt * 64 + aj * 8);
        }
#pragma unroll
        for (int i = 0; i < 8; i++) {
            int k = bkl + 8 * i;
            cp16(st + 16384 + k * 512 + ((bc ^ bkl) << 4),
                 B + (size_t)(kt * 64 + k) * ND + bc * 8);
        }
        asm volatile("cp.async.commit_group;");
    };

    const int KT = KD / 64;
    fill(0); fill(1); fill(2);

    float acc[4][8][4];
#pragma unroll
    for (int f = 0; f < 4; f++)
#pragma unroll
        for (int g = 0; g < 8; g++)
#pragma unroll
            for (int q = 0; q < 4; q++) acc[f][g][q] = 0.f;

    const uint32_t aRowB = (uint32_t)(wm * 64 + ((lane >> 3) & 1) * 8 + ls) * 128;
    const uint32_t aCh   = (uint32_t)(lane >> 4);
    const uint32_t bRowB = (uint32_t)(((lane >> 3) & 1) * 8 + ls) * 512;
    const uint32_t bC0   = (uint32_t)(wn * 8 + (lane >> 4));

#pragma unroll 1
    for (int kt = 0; kt < KT; kt++) {
        const int rem = KT - 1 - kt;
        if (rem >= 2)      asm volatile("cp.async.wait_group 2;");
        else if (rem == 1) asm volatile("cp.async.wait_group 1;");
        else               asm volatile("cp.async.wait_group 0;");
        __syncthreads();
        if (kt + 3 < KT) fill(kt + 3);

        const uint32_t sA = sb + (uint32_t)(kt & 3) * STAGE;
        const uint32_t sB = sA + 16384;
#pragma unroll
        for (int ks = 0; ks < 4; ks++) {
            uint32_t a[4][4], b[4][4];
#pragma unroll
            for (int f = 0; f < 4; f++)
                ldm4(a[f], sA + aRowB + f * 2048 + (((2 * ks + aCh) ^ ls) << 4));
#pragma unroll
            for (int p = 0; p < 4; p++)
                ldm4t(b[p], sB + ks * 8192 + bRowB + (((bC0 + 2 * p) ^ ls) << 4));
#pragma unroll
            for (int f = 0; f < 4; f++)
#pragma unroll
                for (int g = 0; g < 8; g++)
                    mma16816(acc[f][g], a[f], &b[g >> 1][(g & 1) * 2]);
        }
    }

    // ---- epilogue: bias + relu + coalesced stores ----
#pragma unroll
    for (int f = 0; f < 4; f++) {
        const int r0 = row0 + wm * 64 + f * 16 + lq;
        const int r1 = r0 + 8;
#pragma unroll
        for (int g = 0; g < 8; g++) {
            const int col = wn * 64 + g * 8 + 2 * lr;
            float2 bb = *(const float2*)(bias + col);
            float v00 = fmaxf(acc[f][g][0] + bb.x, 0.f);
            float v01 = fmaxf(acc[f][g][1] + bb.y, 0.f);
            float v10 = fmaxf(acc[f][g][2] + bb.x, 0.f);
            float v11 = fmaxf(acc[f][g][3] + bb.y, 0.f);
            if (FIRST) {
                if (r0 < cnt)
                    *(__half2*)(g_hh + (size_t)(base + r0) * ND + col0 + col) = __floats2half2_rn(v00, v01);
                if (r1 < cnt)
                    *(__half2*)(g_hh + (size_t)(base + r1) * ND + col0 + col) = __floats2half2_rn(v10, v11);
            } else {
                if (r0 < cnt)
                    *(float2*)(g_ybuf + (size_t)(base + r0) * ND + col0 + col) = make_float2(v00, v01);
                if (r1 < cnt)
                    *(float2*)(g_ybuf + (size_t)(base + r1) * ND + col0 + col) = make_float2(v10, v11);
            }
        }
    }
}

// ---------------- combine ----------------
__global__ void combine_kernel(float* __restrict__ out) {
    int gid = blockIdx.x * blockDim.x + threadIdx.x;
    if (gid >= N_TOK * OUTD / 4) return;
    int n = gid / (OUTD / 4);
    int c = (gid % (OUTD / 4)) * 4;
    int r0 = g_rowpos[2*n], r1 = g_rowpos[2*n + 1];
    float w0 = g_wgt[r0], w1 = g_wgt[r1];
    float4 y0 = *(const float4*)(g_ybuf + (size_t)r0 * OUTD + c);
    float4 y1 = *(const float4*)(g_ybuf + (size_t)r1 * OUTD + c);
    float4 o;
    o.x = w0*y0.x + w1*y1.x;
    o.y = w0*y0.y + w1*y1.y;
    o.z = w0*y0.z + w1*y1.z;
    o.w = w0*y0.w + w1*y1.w;
    *(float4*)(out + (size_t)n * OUTD + c) = o;
}

// ---------------- launch ----------------
extern "C" void kernel_launch(void* const* d_in, const int* in_sizes, int n_in,
                              void* d_out, int out_size) {
    const float* x  = (const float*)d_in[0];
    const float* Wg = (const float*)d_in[1];
    const float* W1 = (const float*)d_in[2];
    const float* b1 = (const float*)d_in[3];
    const float* W2 = (const float*)d_in[4];
    const float* b2 = (const float*)d_in[5];
    float* out = (float*)d_out;

    static cudaStream_t s1 = nullptr;
    static cudaEvent_t evFork = nullptr, evC1 = nullptr, evC2 = nullptr;
    static bool inited = false;
    if (!inited) {
        cudaStreamCreateWithFlags(&s1, cudaStreamNonBlocking);
        cudaEventCreateWithFlags(&evFork, cudaEventDisableTiming);
        cudaEventCreateWithFlags(&evC1,  cudaEventDisableTiming);
        cudaEventCreateWithFlags(&evC2,  cudaEventDisableTiming);
        cudaFuncSetAttribute(gemm_hmma<DIMD, HID, true>,
                             cudaFuncAttributeMaxDynamicSharedMemorySize, SMEM_TOTAL);
        cudaFuncSetAttribute(gemm_hmma<HID, OUTD, false>,
                             cudaFuncAttributeMaxDynamicSharedMemorySize, SMEM_TOTAL);
        inited = true;
    }

    // fork: weight converts on side stream
    cudaEventRecord(evFork, 0);
    cudaStreamWaitEvent(s1, evFork, 0);
    convert_kernel<true ><<<4096, 256, 0, s1>>>((const float4*)W1, NE * DIMD * HID / 4);
    cudaEventRecord(evC1, s1);
    convert_kernel<false><<<4096, 256, 0, s1>>>((const float4*)W2, NE * HID * OUTD / 4);
    cudaEventRecord(evC2, s1);

    // main: fused gate+convert, plan
    gate_kernel<<<N_TOK / 8, 256>>>(x, Wg);
    plan_kernel<<<1, 1024>>>();

    // GEMM1 (A via perm indirection)
    cudaStreamWaitEvent(0, evC1, 0);
    {
        dim3 grid(RMAX / 128, HID / 256, NE);
        gemm_hmma<DIMD, HID, true><<<grid, 256, SMEM_TOTAL>>>(b1);
    }
    // GEMM2
    cudaStreamWaitEvent(0, evC2, 0);
    {
        dim3 grid(RMAX / 128, OUTD / 256, NE);
        gemm_hmma<HID, OUTD, false><<<grid, 256, SMEM_TOTAL>>>(b2);
    }
    combine_kernel<<<(N_TOK * OUTD / 4 + 255) / 256, 256>>>(out);
}